// round 11
// baseline (speedup 1.0000x reference)
#include <cuda_runtime.h>
#include <cstdint>

#define BB 8
#define FF 2048
#define LL 1024
#define THRESH 0.81f
#define BN_EPS 1e-5f
#define NBLK 256
#define NTHR 256

// scratch (device globals per allocation rules)
__device__ float g_h[BB * FF];       // pooled prelu means
__device__ float g_hbn[BB * FF];     // BN'd h
__device__ float g_dinv[BB * FF];    // rsqrt(degree)
__device__ unsigned g_cnt;           // barrier counter (returns to 0 each barrier)
__device__ volatile unsigned g_sense;// flips per barrier; 2 barriers/launch -> replay-invariant

// Sense-reversing grid barrier. Safe because all NBLK blocks are co-resident
// (__launch_bounds__(NTHR,2), NBLK=256 <= 148*2).
__device__ __forceinline__ void grid_barrier(unsigned* lsense) {
    __syncthreads();
    if (threadIdx.x == 0) {
        const unsigned target = *lsense ^ 1u;
        *lsense = target;
        __threadfence();                       // publish this block's prior writes
        unsigned old = atomicAdd(&g_cnt, 1u);
        if (old == NBLK - 1) {
            g_cnt = 0;                         // reset BEFORE release
            __threadfence();
            g_sense = target;                  // release
        } else {
            while (g_sense != target) __nanosleep(64);
        }
        __threadfence();                       // acquire
    }
    __syncthreads();
}

__global__ void __launch_bounds__(NTHR, 2)
fused_all(const float* __restrict__ x,
          const float* __restrict__ w1p,
          const float* __restrict__ bw,
          const float* __restrict__ bb,
          float* __restrict__ out) {
    __shared__ float sh[FF];       // 8 KB (P2)
    __shared__ unsigned lsense;
    if (threadIdx.x == 0) lsense = 0u;

    const int tid = threadIdx.x;
    const int warp = tid >> 5, lane = tid & 31;

    // ================= P1: prelu + mean over L =================
    // 2048 warps total, 16384 rows -> 8 consecutive rows per warp.
    {
        const float w1 = w1p[0];
        const int gw = blockIdx.x * 8 + warp;       // 0..2047
        #pragma unroll
        for (int j = 0; j < 8; j++) {
            const int row = gw * 8 + j;
            const float4* xr = (const float4*)(x + (size_t)row * LL);
            float4 v[8];
            #pragma unroll
            for (int k = 0; k < 8; k++) v[k] = xr[lane + 32 * k];
            float s = 0.f;
            #pragma unroll
            for (int k = 0; k < 8; k++) {
                s += (v[k].x >= 0.f) ? v[k].x : w1 * v[k].x;
                s += (v[k].y >= 0.f) ? v[k].y : w1 * v[k].y;
                s += (v[k].z >= 0.f) ? v[k].z : w1 * v[k].z;
                s += (v[k].w >= 0.f) ? v[k].w : w1 * v[k].w;
            }
            #pragma unroll
            for (int o = 16; o; o >>= 1) s += __shfl_down_sync(0xffffffffu, s, o);
            if (lane == 0) g_h[row] = s * (1.0f / LL);
        }
    }

    grid_barrier(&lsense);

    // ================= P2: BN (redundant per block) + degree =================
    // block -> (b = bx>>5, slice sl = bx&31 of 64 rows)
    {
        const int b = blockIdx.x >> 5;
        const int sl = blockIdx.x & 31;

        // BN for ALL channels into smem; write own 64-col slice to g_hbn
        #pragma unroll
        for (int c = 0; c < 8; c++) {
            const int f = tid + c * 256;
            float v[BB];
            float mu = 0.f;
            #pragma unroll
            for (int q = 0; q < BB; q++) { v[q] = g_h[q * FF + f]; mu += v[q]; }
            mu *= (1.0f / BB);
            float var = 0.f;
            #pragma unroll
            for (int q = 0; q < BB; q++) { float d = v[q] - mu; var += d * d; }
            var *= (1.0f / BB);
            const float hv = (v[b] - mu) * rsqrtf(var + BN_EPS) * bw[f] + bb[f];
            sh[f] = hv;
            if ((f >> 6) == sl) g_hbn[b * FF + f] = hv;
        }
        __syncthreads();

        // degree: warp w -> 8 rows
        const int nbase = sl * 64 + warp * 8;
        float hn[8], cnt[8];
        #pragma unroll
        for (int r = 0; r < 8; r++) { hn[r] = sh[nbase + r]; cnt[r] = 0.f; }

        const float4* s4 = (const float4*)sh;
        #pragma unroll 2
        for (int i = lane; i < FF / 4; i += 32) {
            float4 v = s4[i];
            #pragma unroll
            for (int r = 0; r < 8; r++) {
                // exact FMUL-then-compare semantics as reference sim > THRESH
                cnt[r] += (hn[r] * v.x > THRESH) ? 1.f : 0.f;
                cnt[r] += (hn[r] * v.y > THRESH) ? 1.f : 0.f;
                cnt[r] += (hn[r] * v.z > THRESH) ? 1.f : 0.f;
                cnt[r] += (hn[r] * v.w > THRESH) ? 1.f : 0.f;
            }
        }
        #pragma unroll
        for (int r = 0; r < 8; r++) {
            #pragma unroll
            for (int o = 16; o; o >>= 1)
                cnt[r] += __shfl_down_sync(0xffffffffu, cnt[r], o);
        }
        if (lane == 0) {
            #pragma unroll
            for (int r = 0; r < 8; r++)
                g_dinv[b * FF + nbase + r] = rsqrtf(cnt[r] + 1.0f); // +1 identity
        }
    }

    grid_barrier(&lsense);

    // ================= P3: expand output (direct STG) =================
    // block -> (b, 64 rows sl*64..+63), 16 tiles of 4 rows.
    {
        const int b = blockIdx.x >> 5;
        const int sl = blockIdx.x & 31;
        const float* __restrict__ hb = g_hbn + b * FF;
        const float* __restrict__ db = g_dinv + b * FF;

        // per-thread m columns: float4 indices q0 = tid, q1 = tid+256
        float hm[8], dm[8];
        #pragma unroll
        for (int j = 0; j < 2; j++) {
            const int q = tid + j * 256;
            float4 h4 = ((const float4*)hb)[q];
            float4 d4 = ((const float4*)db)[q];
            hm[j * 4 + 0] = h4.x; hm[j * 4 + 1] = h4.y;
            hm[j * 4 + 2] = h4.z; hm[j * 4 + 3] = h4.w;
            dm[j * 4 + 0] = d4.x; dm[j * 4 + 1] = d4.y;
            dm[j * 4 + 2] = d4.z; dm[j * 4 + 3] = d4.w;
        }

        float* outb = out + (size_t)b * FF * FF;
        for (int t = 0; t < 16; t++) {
            #pragma unroll
            for (int nn = 0; nn < 4; nn++) {
                const int n = sl * 64 + t * 4 + nn;
                const float hn = hb[n];      // uniform -> broadcast, L1 hit
                const float dn = db[n];
                const float diag = dn * dn;
                float4* orow = (float4*)(outb + (size_t)n * FF);
                #pragma unroll
                for (int j = 0; j < 2; j++) {
                    const int q = tid + j * 256;
                    const int mg = q * 4;
                    float4 r;
                    float* rp = &r.x;
                    #pragma unroll
                    for (int k = 0; k < 4; k++) {
                        float v = (hn * hm[j * 4 + k] > THRESH)
                                      ? dn * dm[j * 4 + k] : 0.f;
                        if (mg + k == n) v += diag;
                        rp[k] = v;
                    }
                    orow[q] = r;
                }
            }
        }
    }
}

extern "C" void kernel_launch(void* const* d_in, const int* in_sizes, int n_in,
                              void* d_out, int out_size) {
    const float* x   = (const float*)d_in[0];
    const float* w1  = (const float*)d_in[1];
    // d_in[2] = prelu2_w: unused — A_hat is provably nonnegative, PReLU is identity
    const float* bnw = (const float*)d_in[3];
    const float* bnb = (const float*)d_in[4];
    float* out = (float*)d_out;

    fused_all<<<NBLK, NTHR>>>(x, w1, bnw, bnb, out);
}

// round 12
// speedup vs baseline: 1.0964x; 1.0964x over previous
#include <cuda_runtime.h>
#include <cstdint>

#define BB 8
#define FF 2048
#define LL 1024
#define THRESH 0.81f
#define BN_EPS 1e-5f

// scratch (device globals per allocation rules)
__device__ float g_h[BB * FF];     // raw pooled prelu means (k1 output)
__device__ float g_hbn[BB * FF];   // BN'd h (k23 output)
__device__ float g_dinv[BB * FF];  // rsqrt(degree)

// ---------------- k1: prelu + mean over L (warp-per-2-rows, MLP=16) --------
// grid = BB*FF/16 = 1024 blocks, 256 threads = 8 warps.
// Each warp reduces 2 consecutive rows; 16 front-batched LDG.128 per lane.
__global__ void k1_rowmean(const float* __restrict__ x,
                           const float* __restrict__ w1p) {
    const float w1 = w1p[0];
    const int warp = threadIdx.x >> 5, lane = threadIdx.x & 31;
    const int gw = blockIdx.x * 8 + warp;          // 0..2047
    const int row0 = gw * 2;
    const float4* xr0 = (const float4*)(x + (size_t)row0 * LL);
    const float4* xr1 = (const float4*)(x + (size_t)(row0 + 1) * LL);

    float4 a[8], c[8];
    #pragma unroll
    for (int j = 0; j < 8; j++) a[j] = xr0[lane + 32 * j];
    #pragma unroll
    for (int j = 0; j < 8; j++) c[j] = xr1[lane + 32 * j];

    float s0 = 0.f, s1 = 0.f;
    #pragma unroll
    for (int j = 0; j < 8; j++) {
        s0 += (a[j].x >= 0.f) ? a[j].x : w1 * a[j].x;
        s0 += (a[j].y >= 0.f) ? a[j].y : w1 * a[j].y;
        s0 += (a[j].z >= 0.f) ? a[j].z : w1 * a[j].z;
        s0 += (a[j].w >= 0.f) ? a[j].w : w1 * a[j].w;
        s1 += (c[j].x >= 0.f) ? c[j].x : w1 * c[j].x;
        s1 += (c[j].y >= 0.f) ? c[j].y : w1 * c[j].y;
        s1 += (c[j].z >= 0.f) ? c[j].z : w1 * c[j].z;
        s1 += (c[j].w >= 0.f) ? c[j].w : w1 * c[j].w;
    }
    #pragma unroll
    for (int o = 16; o; o >>= 1) {
        s0 += __shfl_down_sync(0xffffffffu, s0, o);
        s1 += __shfl_down_sync(0xffffffffu, s1, o);
    }
    if (lane == 0) {
        g_h[row0]     = s0 * (1.0f / LL);
        g_h[row0 + 1] = s1 * (1.0f / LL);
    }
}

// ---------------- k23: fused BatchNorm + degree (R4 measured config) --------
// grid (FF/64, BB) = (32, 8) = 256 blocks, 512 threads = 16 warps.
#define SLICE 64
__global__ void k23_bn_deg(const float* __restrict__ bw,
                           const float* __restrict__ bb) {
    const int b = blockIdx.y;
    __shared__ float sh[FF];
    const int tid = threadIdx.x;

    // BN: 4 channels per thread (coalesced, f = tid + c*512)
    #pragma unroll
    for (int c = 0; c < 4; c++) {
        const int f = tid + c * 512;
        float v[BB];
        float mu = 0.f;
        #pragma unroll
        for (int q = 0; q < BB; q++) { v[q] = g_h[q * FF + f]; mu += v[q]; }
        mu *= (1.0f / BB);
        float var = 0.f;
        #pragma unroll
        for (int q = 0; q < BB; q++) { float d = v[q] - mu; var += d * d; }
        var *= (1.0f / BB);
        const float hv = (v[b] - mu) * rsqrtf(var + BN_EPS) * bw[f] + bb[f];
        sh[f] = hv;
        if ((f >> 6) == (int)blockIdx.x) g_hbn[b * FF + f] = hv;
    }
    __syncthreads();

    // degree count: warp w -> 4 rows
    const int warp = tid >> 5, lane = tid & 31;
    const int nbase = blockIdx.x * SLICE + warp * 4;
    float hn[4], cnt[4] = {0.f, 0.f, 0.f, 0.f};
    #pragma unroll
    for (int r = 0; r < 4; r++) hn[r] = sh[nbase + r];

    const float4* s4 = (const float4*)sh;
    #pragma unroll 4
    for (int i = lane; i < FF / 4; i += 32) {
        float4 v = s4[i];
        #pragma unroll
        for (int r = 0; r < 4; r++) {
            // exact FMUL-then-compare semantics as reference sim > THRESH
            cnt[r] += (hn[r] * v.x > THRESH) ? 1.f : 0.f;
            cnt[r] += (hn[r] * v.y > THRESH) ? 1.f : 0.f;
            cnt[r] += (hn[r] * v.z > THRESH) ? 1.f : 0.f;
            cnt[r] += (hn[r] * v.w > THRESH) ? 1.f : 0.f;
        }
    }
    #pragma unroll
    for (int r = 0; r < 4; r++) {
        #pragma unroll
        for (int o = 16; o; o >>= 1)
            cnt[r] += __shfl_down_sync(0xffffffffu, cnt[r], o);
    }
    if (lane == 0) {
        #pragma unroll
        for (int r = 0; r < 4; r++)
            g_dinv[b * FF + nbase + r] = rsqrtf(cnt[r] + 1.0f);  // +1 identity
    }
}

// ---------------- k4: expand output via smem staging + one-shot bulk TMA ----
// out[b,n,m] = dinv_n*dinv_m*[h_n*h_m > T] + (n==m)*dinv_n^2
// grid (FF/TILE_N, BB) = (512, 8) = 4096 blocks, 256 threads. 32KB tile,
// one cp.async.bulk store per block. (R4/R8 measured: ~21.8us)
#define TILE_N 4
__global__ void k4_out(float* __restrict__ out) {
    __shared__ __align__(128) float tile[TILE_N * FF];  // 32 KB
    const int b = blockIdx.y;
    const int n0 = blockIdx.x * TILE_N;
    const float* __restrict__ hb = g_hbn + b * FF;
    const float* __restrict__ db = g_dinv + b * FF;

    // per-thread m columns: float4 indices q0 = tid, q1 = tid+256
    float hm[8], dm[8];
    #pragma unroll
    for (int j = 0; j < 2; j++) {
        const int q = threadIdx.x + j * 256;
        float4 h4 = ((const float4*)hb)[q];
        float4 d4 = ((const float4*)db)[q];
        hm[j * 4 + 0] = h4.x; hm[j * 4 + 1] = h4.y;
        hm[j * 4 + 2] = h4.z; hm[j * 4 + 3] = h4.w;
        dm[j * 4 + 0] = d4.x; dm[j * 4 + 1] = d4.y;
        dm[j * 4 + 2] = d4.z; dm[j * 4 + 3] = d4.w;
    }

    float4* t4 = (float4*)tile;
    #pragma unroll
    for (int nn = 0; nn < TILE_N; nn++) {
        const int n = n0 + nn;
        const float hn = hb[n];        // uniform -> broadcast, L1 hit
        const float dn = db[n];
        const float diag = dn * dn;
        #pragma unroll
        for (int j = 0; j < 2; j++) {
            const int q = threadIdx.x + j * 256;
            const int mg = q * 4;
            float4 r;
            float* rp = &r.x;
            #pragma unroll
            for (int k = 0; k < 4; k++) {
                float v = (hn * hm[j * 4 + k] > THRESH) ? dn * dm[j * 4 + k] : 0.f;
                if (mg + k == n) v += diag;
                rp[k] = v;
            }
            t4[nn * (FF / 4) + q] = r;
        }
    }
    __syncthreads();

    if (threadIdx.x == 0) {
        asm volatile("fence.proxy.async.shared::cta;" ::: "memory");
        uint32_t saddr;
        asm("{ .reg .u64 t; cvta.to.shared.u64 t, %1; cvt.u32.u64 %0, t; }"
            : "=r"(saddr) : "l"(tile));
        float* gdst = out + (size_t)b * FF * FF + (size_t)n0 * FF;
        const unsigned bytes = TILE_N * FF * 4;  // 32768
        asm volatile(
            "cp.async.bulk.global.shared::cta.bulk_group [%0], [%1], %2;"
            :: "l"(gdst), "r"(saddr), "r"(bytes) : "memory");
        asm volatile("cp.async.bulk.commit_group;" ::: "memory");
        asm volatile("cp.async.bulk.wait_group.read 0;" ::: "memory");
    }
}

extern "C" void kernel_launch(void* const* d_in, const int* in_sizes, int n_in,
                              void* d_out, int out_size) {
    const float* x   = (const float*)d_in[0];
    const float* w1  = (const float*)d_in[1];
    // d_in[2] = prelu2_w: unused — A_hat is provably nonnegative, PReLU is identity
    const float* bnw = (const float*)d_in[3];
    const float* bnb = (const float*)d_in[4];
    float* out = (float*)d_out;

    k1_rowmean<<<BB * FF / 16, 256>>>(x, w1);
    k23_bn_deg<<<dim3(FF / SLICE, BB), 512>>>(bnw, bnb);
    k4_out<<<dim3(FF / TILE_N, BB), 256>>>(out);
}